// round 5
// baseline (speedup 1.0000x reference)
#include <cuda_runtime.h>

#define EMBED 1024
#define FFN_DIM 4096
#define VEC4 (EMBED / 4)     // 256 float4 per row
#define EPS 1e-5f
#define ROWS_PER_BLOCK 16    // 8 iterations x 2 rows
#define ITERS (ROWS_PER_BLOCK / 2)

// Scratch (no allocations allowed)
__device__ __align__(16) float d_h[FFN_DIM];    // relu(w2 @ cvec_ffn)
__device__ __align__(16) float d_a[EMBED];      // attn constant vector
__device__ __align__(16) float d_b1f[EMBED];    // ln1_b + w_out @ h

__device__ __forceinline__ void circuit4(const float* __restrict__ p, float* out) {
    float c0 = cosf(p[0]), c1 = cosf(p[1]), c2 = cosf(p[2]), c3 = cosf(p[3]);
    out[0] = c1 * c2 * c3;
    out[1] = c0 * c1;
    out[2] = c0 * c1 * c2;
    out[3] = c0 * c1 * c2 * c3;
}

// kH: 16 blocks, h = relu(w2 @ cvec_ffn)
__global__ void __launch_bounds__(256) kH(const float* __restrict__ w2,
                                          const float* __restrict__ ffn_p) {
    float cf[4];
    circuit4(ffn_p, cf);
    int k = blockIdx.x * 256 + threadIdx.x;
    float4 w = reinterpret_cast<const float4*>(w2)[k];   // w2 is [FFN,4]
    d_h[k] = fmaxf(w.x * cf[0] + w.y * cf[1] + w.z * cf[2] + w.w * cf[3], 0.0f);
}

// kF: blocks 0..1023: d_b1f[e] = ln1_b[e] + w_out[e,:].h  (block-per-e, h L2-hot)
//     blocks 1024..1151: d_a (warp-per-element, 8 e per block)
__global__ void __launch_bounds__(256) kF(const float* __restrict__ w_out,
                                          const float* __restrict__ ln1_b,
                                          const float* __restrict__ w_mix,
                                          const float* __restrict__ attn_p) {
    const int t = threadIdx.x;
    const int warp = t >> 5, lane = t & 31;
    if (blockIdx.x < 1024) {
        const int e = blockIdx.x;
        const float4* wo = reinterpret_cast<const float4*>(w_out + (size_t)e * FFN_DIM);
        const float4* h4 = reinterpret_cast<const float4*>(d_h);
        float sf = 0.0f;
#pragma unroll
        for (int i = 0; i < 4; i++) {
            float4 w = wo[t + i * 256];
            float4 hv = h4[t + i * 256];
            sf += w.x * hv.x + w.y * hv.y + w.z * hv.z + w.w * hv.w;
        }
#pragma unroll
        for (int o = 16; o > 0; o >>= 1)
            sf += __shfl_xor_sync(0xffffffffu, sf, o);
        __shared__ float sh[8];
        if (lane == 0) sh[warp] = sf;
        __syncthreads();
        if (t == 0) {
            float tot = 0.0f;
#pragma unroll
            for (int i = 0; i < 8; i++) tot += sh[i];
            d_b1f[e] = ln1_b[e] + tot;
        }
    } else {
        float ca[4];
        circuit4(attn_p, ca);
        const int e = (blockIdx.x - 1024) * 8 + warp;
        const float4* wm = reinterpret_cast<const float4*>(w_mix + (size_t)e * EMBED);
        float sa = 0.0f;
#pragma unroll
        for (int i = 0; i < 8; i++) {
            float4 w = wm[lane + 32 * i];
            sa += w.x * ca[0] + w.y * ca[1] + w.z * ca[2] + w.w * ca[3];
        }
#pragma unroll
        for (int o = 16; o > 0; o >>= 1)
            sa += __shfl_xor_sync(0xffffffffu, sa, o);
        if (lane == 0) d_a[e] = sa;
    }
}

// kMain: 512 threads = 2 rows per iteration (warps 0-7 row A, 8-15 row B).
// Single fused reduction pass (6 accumulators) gives BOTH LayerNorm stats with
// ONE barrier per iteration (0.5 per row). Constants live in registers.
//   u  = x + a
//   z  = g1*(u-m1)*r1 + b1f
//   out= g2*(z-m2)*r2 + b2
__global__ void __launch_bounds__(512, 2) kMain(const float4* __restrict__ x,
                                                const float4* __restrict__ g1,
                                                const float4* __restrict__ g2,
                                                const float4* __restrict__ b2,
                                                float4* __restrict__ out) {
    const int t = threadIdx.x;
    const int c = t & 255;          // column (float4 index within row)
    const int half = t >> 8;        // 0 = row A, 1 = row B
    const int warp = t >> 5, lane = t & 31;
    __shared__ float part[2][16 * 6];   // [buffer][warp*6 + k]

    // Register-resident constants (20 regs)
    const float4 A  = __ldg(&reinterpret_cast<const float4*>(d_a)[c]);
    const float4 G1 = __ldg(&g1[c]);
    const float4 B1 = __ldg(&reinterpret_cast<const float4*>(d_b1f)[c]);
    const float4 G2 = __ldg(&g2[c]);
    const float4 B2 = __ldg(&b2[c]);

    // ---- one-time scalar sums over the row-invariant vectors ----
    // Sg=Σg1, Sgq=Σg1², Sgb=Σg1·b1f, Sb=Σb1f, Sbb=Σb1f²  (half 0 contributes)
    float p0 = 0.f, p1 = 0.f, p2 = 0.f, p3 = 0.f, p4 = 0.f;
    if (half == 0) {
        p0 = G1.x + G1.y + G1.z + G1.w;
        p1 = G1.x*G1.x + G1.y*G1.y + G1.z*G1.z + G1.w*G1.w;
        p2 = G1.x*B1.x + G1.y*B1.y + G1.z*B1.z + G1.w*B1.w;
        p3 = B1.x + B1.y + B1.z + B1.w;
        p4 = B1.x*B1.x + B1.y*B1.y + B1.z*B1.z + B1.w*B1.w;
    }
#pragma unroll
    for (int o = 16; o > 0; o >>= 1) {
        p0 += __shfl_xor_sync(0xffffffffu, p0, o);
        p1 += __shfl_xor_sync(0xffffffffu, p1, o);
        p2 += __shfl_xor_sync(0xffffffffu, p2, o);
        p3 += __shfl_xor_sync(0xffffffffu, p3, o);
        p4 += __shfl_xor_sync(0xffffffffu, p4, o);
    }
    if (half == 0 && lane == 0) {
        part[0][warp * 6 + 0] = p0; part[0][warp * 6 + 1] = p1;
        part[0][warp * 6 + 2] = p2; part[0][warp * 6 + 3] = p3;
        part[0][warp * 6 + 4] = p4;
    }
    __syncthreads();
    float Sg = 0.f, Sgq = 0.f, Sgb = 0.f, Sb = 0.f, Sbb = 0.f;
#pragma unroll
    for (int w = 0; w < 8; w++) {
        Sg  += part[0][w * 6 + 0];
        Sgq += part[0][w * 6 + 1];
        Sgb += part[0][w * 6 + 2];
        Sb  += part[0][w * 6 + 3];
        Sbb += part[0][w * 6 + 4];
    }
    __syncthreads();   // protect part[0] before loop reuse

    // ---- main loop: 2 rows per iteration, 1 barrier per iteration ----
    const size_t base = (size_t)blockIdx.x * ROWS_PER_BLOCK * VEC4;
    const float4* __restrict__ xp = x + base + (size_t)half * VEC4 + c;
    float4* __restrict__ op = out + base + (size_t)half * VEC4 + c;

    float4 xv = __ldcs(xp);
#pragma unroll 1
    for (int i = 0; i < ITERS; i++) {
        const int buf = i & 1;
        float4 u;
        u.x = xv.x + A.x; u.y = xv.y + A.y; u.z = xv.z + A.z; u.w = xv.w + A.w;

        float4 xn;
        if (i + 1 < ITERS) xn = __ldcs(xp + (size_t)(i + 1) * 2 * VEC4);

        // 6 accumulators: Σu, Σu², Σg·u, Σg²·u, Σg²·u², Σg·b·u
        float a0 = u.x + u.y + u.z + u.w;
        float a1 = u.x*u.x + u.y*u.y + u.z*u.z + u.w*u.w;
        float a2 = G1.x*u.x + G1.y*u.y + G1.z*u.z + G1.w*u.w;
        float gx = G1.x*G1.x, gy = G1.y*G1.y, gz = G1.z*G1.z, gw = G1.w*G1.w;
        float a3 = gx*u.x + gy*u.y + gz*u.z + gw*u.w;
        float a4 = gx*u.x*u.x + gy*u.y*u.y + gz*u.z*u.z + gw*u.w*u.w;
        float a5 = G1.x*B1.x*u.x + G1.y*B1.y*u.y + G1.z*B1.z*u.z + G1.w*B1.w*u.w;

#pragma unroll
        for (int o = 16; o > 0; o >>= 1) {
            a0 += __shfl_xor_sync(0xffffffffu, a0, o);
            a1 += __shfl_xor_sync(0xffffffffu, a1, o);
            a2 += __shfl_xor_sync(0xffffffffu, a2, o);
            a3 += __shfl_xor_sync(0xffffffffu, a3, o);
            a4 += __shfl_xor_sync(0xffffffffu, a4, o);
            a5 += __shfl_xor_sync(0xffffffffu, a5, o);
        }
        if (lane == 0) {
            float* pp = &part[buf][warp * 6];
            pp[0] = a0; pp[1] = a1; pp[2] = a2; pp[3] = a3; pp[4] = a4; pp[5] = a5;
        }
        __syncthreads();

        const float* pb = &part[buf][half * 8 * 6];
        float s0 = 0.f, s1 = 0.f, s2 = 0.f, s3 = 0.f, s4 = 0.f, s5 = 0.f;
#pragma unroll
        for (int w = 0; w < 8; w++) {
            s0 += pb[w * 6 + 0]; s1 += pb[w * 6 + 1]; s2 += pb[w * 6 + 2];
            s3 += pb[w * 6 + 3]; s4 += pb[w * 6 + 4]; s5 += pb[w * 6 + 5];
        }

        const float invN = 1.0f / EMBED;
        float m1 = s0 * invN;
        float r1 = rsqrtf(s1 * invN - m1 * m1 + EPS);
        float sz  = r1 * (s2 - m1 * Sg) + Sb;
        float m2 = sz * invN;
        float szz = r1 * r1 * (s4 - 2.f * m1 * s3 + m1 * m1 * Sgq)
                  + 2.f * r1 * (s5 - m1 * Sgb) + Sbb;
        float r2 = rsqrtf(szz * invN - m2 * m2 + EPS);

        float4 o4;
        {
            float zx = G1.x * (u.x - m1) * r1 + B1.x;
            float zy = G1.y * (u.y - m1) * r1 + B1.y;
            float zz2 = G1.z * (u.z - m1) * r1 + B1.z;
            float zw = G1.w * (u.w - m1) * r1 + B1.w;
            o4.x = G2.x * (zx - m2) * r2 + B2.x;
            o4.y = G2.y * (zy - m2) * r2 + B2.y;
            o4.z = G2.z * (zz2 - m2) * r2 + B2.z;
            o4.w = G2.w * (zw - m2) * r2 + B2.w;
        }
        __stcs(op + (size_t)i * 2 * VEC4, o4);
        xv = xn;
    }
}

extern "C" void kernel_launch(void* const* d_in, const int* in_sizes, int n_in,
                              void* d_out, int out_size) {
    // metadata order: x, wq, wk, wv, w_mix, attn_params, w1, w2, w_out,
    //                 ffn_params, ln1_g, ln1_b, ln2_g, ln2_b
    const float* x      = (const float*)d_in[0];
    const float* w_mix  = (const float*)d_in[4];
    const float* attn_p = (const float*)d_in[5];
    const float* w2     = (const float*)d_in[7];
    const float* w_out  = (const float*)d_in[8];
    const float* ffn_p  = (const float*)d_in[9];
    const float* ln1_g  = (const float*)d_in[10];
    const float* ln1_b  = (const float*)d_in[11];
    const float* ln2_g  = (const float*)d_in[12];
    const float* ln2_b  = (const float*)d_in[13];

    const int n_rows = in_sizes[0] / EMBED;  // B*S = 16384

    kH<<<FFN_DIM / 256, 256>>>(w2, ffn_p);
    kF<<<1024 + EMBED / 8, 256>>>(w_out, ln1_b, w_mix, attn_p);
    kMain<<<n_rows / ROWS_PER_BLOCK, 512>>>(
        (const float4*)x,
        (const float4*)ln1_g,
        (const float4*)ln2_g, (const float4*)ln2_b,
        (float4*)d_out);
}